// round 7
// baseline (speedup 1.0000x reference)
#include <cuda_runtime.h>
#include <cuda_bf16.h>

// SKA: spatially-varying 3x3 grouped conv.
// x: (B=8, C=64, H=128, W=128) f32
// w: (B=8, C_w=8, 9, H, W) f32
// out[b, g*8+cw, h, col] = sum_{i,j} x_pad[b, g*8+cw, h+i-1, col+j-1] * w[b, cw, i*3+j, h, col]
//
// Block = 128 threads = 4 warps, all serving one (b, cw, h). Warp q handles
// groups {q, q+4}. All 4 warps read the SAME 9 weight rows -> L1 reuse.
// Each thread issues 15 independent LDG.128 up front (9 w + 6 x).
// Output stores use st.global.wt (write-through, no L2 allocate) so the
// 33.5MB output stream does not evict the 71MB x+w read set from the 126MB
// L2 -- across graph replays x/w stay L2-resident, cutting DRAM reads.

#define B_   8
#define C_   64
#define H_   128
#define W_   128
#define CW_  8
#define G_   8
#define HW_  (H_ * W_)

__device__ __forceinline__ void stwt_float4(float* p, float4 v) {
    asm volatile("st.global.wt.v4.f32 [%0], {%1, %2, %3, %4};"
                 :: "l"(p), "f"(v.x), "f"(v.y), "f"(v.z), "f"(v.w) : "memory");
}

__global__ void __launch_bounds__(128) ska_kernel(
    const float* __restrict__ x,
    const float* __restrict__ w,
    float* __restrict__ out)
{
    int tid  = threadIdx.x;
    int lane = tid & 31;
    int q    = tid >> 5;              // warp id in block: groups q and q+4
    int blk  = blockIdx.x;
    int h    = blk & 127;
    int cw   = (blk >> 7) & 7;
    int b    = blk >> 10;
    int col0 = lane << 2;

    const bool top = (h > 0);
    const bool bot = (h < H_ - 1);
    const float4 z4 = make_float4(0.f, 0.f, 0.f, 0.f);

    const int c0 = q * CW_ + cw;
    const int c1 = (q + 4) * CW_ + cw;
    const float* xr0 = x + ((size_t)(b * C_ + c0)) * HW_ + h * W_ + col0;
    const float* xr1 = x + ((size_t)(b * C_ + c1)) * HW_ + h * W_ + col0;

    // ---- issue all 15 independent loads up front ----
    float4 v[2][3];
    v[0][1] = *reinterpret_cast<const float4*>(xr0);
    v[1][1] = *reinterpret_cast<const float4*>(xr1);
    v[0][0] = top ? *reinterpret_cast<const float4*>(xr0 - W_) : z4;
    v[1][0] = top ? *reinterpret_cast<const float4*>(xr1 - W_) : z4;
    v[0][2] = bot ? *reinterpret_cast<const float4*>(xr0 + W_) : z4;
    v[1][2] = bot ? *reinterpret_cast<const float4*>(xr1 + W_) : z4;

    const float* wbase = w + ((size_t)(b * CW_ + cw) * 9) * HW_ + h * W_ + col0;
    float4 wv[9];
#pragma unroll
    for (int k = 0; k < 9; k++) {
        wv[k] = *reinterpret_cast<const float4*>(wbase + (size_t)k * HW_);
    }

    float* ob = out + (size_t)b * C_ * HW_ + h * W_ + col0;

#pragma unroll
    for (int p = 0; p < 2; p++) {
        float acc0 = 0.f, acc1 = 0.f, acc2 = 0.f, acc3 = 0.f;
#pragma unroll
        for (int di = 0; di < 3; di++) {
            float L = __shfl_up_sync(0xffffffffu, v[p][di].w, 1);
            float R = __shfl_down_sync(0xffffffffu, v[p][di].x, 1);
            if (lane == 0)  L = 0.f;
            if (lane == 31) R = 0.f;

            float4 wl = wv[di * 3 + 0];
            float4 wc = wv[di * 3 + 1];
            float4 wr = wv[di * 3 + 2];

            acc0 = fmaf(L,          wl.x, acc0);
            acc0 = fmaf(v[p][di].x, wc.x, acc0);
            acc0 = fmaf(v[p][di].y, wr.x, acc0);

            acc1 = fmaf(v[p][di].x, wl.y, acc1);
            acc1 = fmaf(v[p][di].y, wc.y, acc1);
            acc1 = fmaf(v[p][di].z, wr.y, acc1);

            acc2 = fmaf(v[p][di].y, wl.z, acc2);
            acc2 = fmaf(v[p][di].z, wc.z, acc2);
            acc2 = fmaf(v[p][di].w, wr.z, acc2);

            acc3 = fmaf(v[p][di].z, wl.w, acc3);
            acc3 = fmaf(v[p][di].w, wc.w, acc3);
            acc3 = fmaf(R,          wr.w, acc3);
        }

        int c = (q + p * 4) * CW_ + cw;
        float4 o;
        o.x = acc0; o.y = acc1; o.z = acc2; o.w = acc3;
        stwt_float4(ob + (size_t)c * HW_, o);
    }
}

extern "C" void kernel_launch(void* const* d_in, const int* in_sizes, int n_in,
                              void* d_out, int out_size) {
    const float* x = (const float*)d_in[0];
    const float* w = (const float*)d_in[1];
    float* out = (float*)d_out;

    int blocks = B_ * CW_ * H_;   // 8192 blocks
    ska_kernel<<<blocks, 128>>>(x, w, out);
}

// round 8
// speedup vs baseline: 1.1098x; 1.1098x over previous
#include <cuda_runtime.h>
#include <cuda_bf16.h>

// SKA: spatially-varying 3x3 grouped conv.
// x: (B=8, C=64, H=128, W=128) f32
// w: (B=8, C_w=8, 9, H, W) f32
// out[b, g*8+cw, h, col] = sum_{i,j} x_pad[..., h+i-1, col+j-1] * w[b, cw, i*3+j, h, col]
//
// Persistent blocks (456 = ~3/SM), each grid-striding over the 8192 (b,cw,h)
// tiles with a REGISTER DOUBLE BUFFER: loads for tile t+stride are issued
// before computing tile t, so every warp always has ~15 LDG.128 outstanding.
// Block = 128 threads = 4 warps; warp q computes groups {q, q+4}; lane = 4-wide
// column chunk (32 lanes x 4 = full W=128 row); horizontal halo via shuffle.

#define B_   8
#define C_   64
#define H_   128
#define W_   128
#define CW_  8
#define G_   8
#define HW_  (H_ * W_)
#define NTILES (B_ * CW_ * H_)   // 8192
#define GRID_  456               // ~3 blocks per SM (152 SMs)

struct TileBuf {
    float4 v[2][3];   // x rows for the 2 groups this warp owns
    float4 wv[9];     // 9 per-pixel weights (shared by both groups)
};

__device__ __forceinline__ void load_tile(
    TileBuf& tb, int t, int lane, int q,
    const float* __restrict__ x, const float* __restrict__ w)
{
    int h  = t & 127;
    int cw = (t >> 7) & 7;
    int b  = t >> 10;
    int col0 = lane << 2;

    const bool top = (h > 0);
    const bool bot = (h < H_ - 1);
    const float4 z4 = make_float4(0.f, 0.f, 0.f, 0.f);

    const int c0 = q * CW_ + cw;
    const int c1 = (q + 4) * CW_ + cw;
    const float* xr0 = x + ((size_t)(b * C_ + c0)) * HW_ + h * W_ + col0;
    const float* xr1 = x + ((size_t)(b * C_ + c1)) * HW_ + h * W_ + col0;

    tb.v[0][1] = *reinterpret_cast<const float4*>(xr0);
    tb.v[1][1] = *reinterpret_cast<const float4*>(xr1);
    tb.v[0][0] = top ? *reinterpret_cast<const float4*>(xr0 - W_) : z4;
    tb.v[1][0] = top ? *reinterpret_cast<const float4*>(xr1 - W_) : z4;
    tb.v[0][2] = bot ? *reinterpret_cast<const float4*>(xr0 + W_) : z4;
    tb.v[1][2] = bot ? *reinterpret_cast<const float4*>(xr1 + W_) : z4;

    const float* wbase = w + ((size_t)(b * CW_ + cw) * 9) * HW_ + h * W_ + col0;
#pragma unroll
    for (int k = 0; k < 9; k++) {
        tb.wv[k] = *reinterpret_cast<const float4*>(wbase + (size_t)k * HW_);
    }
}

__device__ __forceinline__ void compute_store(
    const TileBuf& tb, int t, int lane, int q, float* __restrict__ out)
{
    int h  = t & 127;
    int cw = (t >> 7) & 7;
    int b  = t >> 10;
    int col0 = lane << 2;

    float* ob = out + (size_t)b * C_ * HW_ + h * W_ + col0;

#pragma unroll
    for (int p = 0; p < 2; p++) {
        float acc0 = 0.f, acc1 = 0.f, acc2 = 0.f, acc3 = 0.f;
#pragma unroll
        for (int di = 0; di < 3; di++) {
            float4 vd = tb.v[p][di];
            float L = __shfl_up_sync(0xffffffffu, vd.w, 1);
            float R = __shfl_down_sync(0xffffffffu, vd.x, 1);
            if (lane == 0)  L = 0.f;
            if (lane == 31) R = 0.f;

            float4 wl = tb.wv[di * 3 + 0];
            float4 wc = tb.wv[di * 3 + 1];
            float4 wr = tb.wv[di * 3 + 2];

            acc0 = fmaf(L,    wl.x, acc0);
            acc0 = fmaf(vd.x, wc.x, acc0);
            acc0 = fmaf(vd.y, wr.x, acc0);

            acc1 = fmaf(vd.x, wl.y, acc1);
            acc1 = fmaf(vd.y, wc.y, acc1);
            acc1 = fmaf(vd.z, wr.y, acc1);

            acc2 = fmaf(vd.y, wl.z, acc2);
            acc2 = fmaf(vd.z, wc.z, acc2);
            acc2 = fmaf(vd.w, wr.z, acc2);

            acc3 = fmaf(vd.z, wl.w, acc3);
            acc3 = fmaf(vd.w, wc.w, acc3);
            acc3 = fmaf(R,    wr.w, acc3);
        }

        int c = (q + p * 4) * CW_ + cw;
        float4 o;
        o.x = acc0; o.y = acc1; o.z = acc2; o.w = acc3;
        *reinterpret_cast<float4*>(ob + (size_t)c * HW_) = o;
    }
}

__global__ void __launch_bounds__(128, 3) ska_kernel(
    const float* __restrict__ x,
    const float* __restrict__ w,
    float* __restrict__ out)
{
    const int tid    = threadIdx.x;
    const int lane   = tid & 31;
    const int q      = tid >> 5;
    const int stride = gridDim.x;

    TileBuf A, B;

    int tA = blockIdx.x;            // < NTILES since grid <= NTILES
    load_tile(A, tA, lane, q, x, w);

    for (;;) {
        int tB = tA + stride;
        if (tB < NTILES) load_tile(B, tB, lane, q, x, w);
        compute_store(A, tA, lane, q, out);
        if (tB >= NTILES) break;

        tA = tB + stride;
        if (tA < NTILES) load_tile(A, tA, lane, q, x, w);
        compute_store(B, tB, lane, q, out);
        if (tA >= NTILES) break;
    }
}

extern "C" void kernel_launch(void* const* d_in, const int* in_sizes, int n_in,
                              void* d_out, int out_size) {
    const float* x = (const float*)d_in[0];
    const float* w = (const float*)d_in[1];
    float* out = (float*)d_out;

    ska_kernel<<<GRID_, 128>>>(x, w, out);
}

// round 10
// speedup vs baseline: 1.3607x; 1.2262x over previous
#include <cuda_runtime.h>
#include <cuda_bf16.h>
#include <cstdint>

// SKA: spatially-varying 3x3 grouped conv.
// x: (B=8, C=64, H=128, W=128) f32
// w: (B=8, C_w=8, 9, H, W) f32
// out[b, g*8+cw, h, col] = sum_{i,j} x_pad[..., h+i-1, col+j-1] * w[b, cw, i*3+j, h, col]
//
// Persistent blocks (456 = 3/SM) grid-striding over 8192 (b,cw,h) tiles with a
// register double buffer (R8 skeleton). L2 residency shaping via createpolicy
// + cache_hint (ptxas on sm_103a rejects bare .L2::evict_* on v4.f32):
//   - x/w loads:  ld.global.nc.L2::cache_hint  with evict_last  policy
//   - out stores: st.global.L2::cache_hint     with evict_first policy
// Read set x+w = 71 MB fits the 126 MB L2 across graph replays if the 33.5 MB
// write stream is the eviction victim instead.

#define B_   8
#define C_   64
#define H_   128
#define W_   128
#define CW_  8
#define G_   8
#define HW_  (H_ * W_)
#define NTILES (B_ * CW_ * H_)   // 8192
#define GRID_  456               // ~3 blocks per SM

__device__ __forceinline__ float4 ldg_pol(const float* p, uint64_t pol) {
    float4 v;
    asm volatile("ld.global.nc.L2::cache_hint.v4.f32 {%0,%1,%2,%3}, [%4], %5;"
                 : "=f"(v.x), "=f"(v.y), "=f"(v.z), "=f"(v.w)
                 : "l"(p), "l"(pol));
    return v;
}

__device__ __forceinline__ void stg_pol(float* p, float4 v, uint64_t pol) {
    asm volatile("st.global.L2::cache_hint.v4.f32 [%0], {%1,%2,%3,%4}, %5;"
                 :: "l"(p), "f"(v.x), "f"(v.y), "f"(v.z), "f"(v.w), "l"(pol)
                 : "memory");
}

struct TileBuf {
    float4 v[2][3];   // x rows for the 2 groups this warp owns
    float4 wv[9];     // 9 per-pixel weights (shared by both groups)
};

__device__ __forceinline__ void load_tile(
    TileBuf& tb, int t, int lane, int q,
    const float* __restrict__ x, const float* __restrict__ w, uint64_t pol_el)
{
    int h  = t & 127;
    int cw = (t >> 7) & 7;
    int b  = t >> 10;
    int col0 = lane << 2;

    const bool top = (h > 0);
    const bool bot = (h < H_ - 1);
    const float4 z4 = make_float4(0.f, 0.f, 0.f, 0.f);

    const int c0 = q * CW_ + cw;
    const int c1 = (q + 4) * CW_ + cw;
    const float* xr0 = x + ((size_t)(b * C_ + c0)) * HW_ + h * W_ + col0;
    const float* xr1 = x + ((size_t)(b * C_ + c1)) * HW_ + h * W_ + col0;

    tb.v[0][1] = ldg_pol(xr0, pol_el);
    tb.v[1][1] = ldg_pol(xr1, pol_el);
    tb.v[0][0] = top ? ldg_pol(xr0 - W_, pol_el) : z4;
    tb.v[1][0] = top ? ldg_pol(xr1 - W_, pol_el) : z4;
    tb.v[0][2] = bot ? ldg_pol(xr0 + W_, pol_el) : z4;
    tb.v[1][2] = bot ? ldg_pol(xr1 + W_, pol_el) : z4;

    const float* wbase = w + ((size_t)(b * CW_ + cw) * 9) * HW_ + h * W_ + col0;
#pragma unroll
    for (int k = 0; k < 9; k++) {
        tb.wv[k] = ldg_pol(wbase + (size_t)k * HW_, pol_el);
    }
}

__device__ __forceinline__ void compute_store(
    const TileBuf& tb, int t, int lane, int q, float* __restrict__ out,
    uint64_t pol_ef)
{
    int h  = t & 127;
    int cw = (t >> 7) & 7;
    int b  = t >> 10;
    int col0 = lane << 2;

    float* ob = out + (size_t)b * C_ * HW_ + h * W_ + col0;

#pragma unroll
    for (int p = 0; p < 2; p++) {
        float acc0 = 0.f, acc1 = 0.f, acc2 = 0.f, acc3 = 0.f;
#pragma unroll
        for (int di = 0; di < 3; di++) {
            float4 vd = tb.v[p][di];
            float L = __shfl_up_sync(0xffffffffu, vd.w, 1);
            float R = __shfl_down_sync(0xffffffffu, vd.x, 1);
            if (lane == 0)  L = 0.f;
            if (lane == 31) R = 0.f;

            float4 wl = tb.wv[di * 3 + 0];
            float4 wc = tb.wv[di * 3 + 1];
            float4 wr = tb.wv[di * 3 + 2];

            acc0 = fmaf(L,    wl.x, acc0);
            acc0 = fmaf(vd.x, wc.x, acc0);
            acc0 = fmaf(vd.y, wr.x, acc0);

            acc1 = fmaf(vd.x, wl.y, acc1);
            acc1 = fmaf(vd.y, wc.y, acc1);
            acc1 = fmaf(vd.z, wr.y, acc1);

            acc2 = fmaf(vd.y, wl.z, acc2);
            acc2 = fmaf(vd.z, wc.z, acc2);
            acc2 = fmaf(vd.w, wr.z, acc2);

            acc3 = fmaf(vd.z, wl.w, acc3);
            acc3 = fmaf(vd.w, wc.w, acc3);
            acc3 = fmaf(R,    wr.w, acc3);
        }

        int c = (q + p * 4) * CW_ + cw;
        float4 o;
        o.x = acc0; o.y = acc1; o.z = acc2; o.w = acc3;
        stg_pol(ob + (size_t)c * HW_, o, pol_ef);
    }
}

__global__ void __launch_bounds__(128, 3) ska_kernel(
    const float* __restrict__ x,
    const float* __restrict__ w,
    float* __restrict__ out)
{
    const int tid    = threadIdx.x;
    const int lane   = tid & 31;
    const int q      = tid >> 5;
    const int stride = gridDim.x;

    uint64_t pol_el, pol_ef;
    asm volatile("createpolicy.fractional.L2::evict_last.b64 %0, 1.0;"  : "=l"(pol_el));
    asm volatile("createpolicy.fractional.L2::evict_first.b64 %0, 1.0;" : "=l"(pol_ef));

    TileBuf A, B;

    int tA = blockIdx.x;            // < NTILES since grid <= NTILES
    load_tile(A, tA, lane, q, x, w, pol_el);

    for (;;) {
        int tB = tA + stride;
        if (tB < NTILES) load_tile(B, tB, lane, q, x, w, pol_el);
        compute_store(A, tA, lane, q, out, pol_ef);
        if (tB >= NTILES) break;

        tA = tB + stride;
        if (tA < NTILES) load_tile(A, tA, lane, q, x, w, pol_el);
        compute_store(B, tB, lane, q, out, pol_ef);
        if (tA >= NTILES) break;
    }
}

extern "C" void kernel_launch(void* const* d_in, const int* in_sizes, int n_in,
                              void* d_out, int out_size) {
    const float* x = (const float*)d_in[0];
    const float* w = (const float*)d_in[1];
    float* out = (float*)d_out;

    ska_kernel<<<GRID_, 128>>>(x, w, out);
}